// round 16
// baseline (speedup 1.0000x reference)
#include <cuda_runtime.h>

// LSTM forward, GB300 sm_103a, fp32 with packed fma.rn.f32x2 (FFMA2).
//
// R15: validated model — smem crossbar charges DELIVERED bytes (L1% x dur
// matched delivered-bytes/128B on R14 exactly). All prior variants delivered
// ~5.5MB/SM/step => 24us crossbar floor. Fix = fatter thread tile:
// 8 cols x 8 batch per thread (1.0 B/MAC, was 2.5). One warp covers the whole
// CTA output tile; 8 warps = 8-way K-split (128 k each), warp-synchronous
// double-buffered staging (NO block syncs in main loop). Partials combined in
// 8 smem rounds; gx added in the epilogue. Crossbar and FFMA2 floors both
// ~16.4k cyc => ~9us ideal step.

#define BATCH 64
#define TT    512
#define EMBD  512
#define HID   1024
#define G4    4096

typedef unsigned long long ull;

// ---------------- device scratch (static only — harness rule) --------------
__device__ float g_Wxp[EMBD * G4];                 //  8 MB packed Wx  [k][c]
__device__ float g_Whp2[128 * HID * 32];           // 16 MB packed Wh  [cb][k][cc]
__device__ float g_bp[G4];
__device__ float g_GX[(size_t)TT * G4 * BATCH];    // 512 MB gates_x (+bias) [t][c][b]
__device__ float g_H0[HID * BATCH];                // hT ping  [k][b]
__device__ float g_H1[HID * BATCH];                // hT pong
__device__ float g_C [HID * BATCH];                // cT

// ---------------- packed fp32x2 helpers ------------------------------------
__device__ __forceinline__ ull ffma2(ull a, ull b, ull c) {
    ull d;
    asm("fma.rn.f32x2 %0, %1, %2, %3;" : "=l"(d) : "l"(a), "l"(b), "l"(c));
    return d;
}
__device__ __forceinline__ ull add2(ull a, ull b) {
    ull d;
    asm("add.rn.f32x2 %0, %1, %2;" : "=l"(d) : "l"(a), "l"(b));
    return d;
}
__device__ __forceinline__ ull pack2(float x, float y) {
    ull r;
    asm("mov.b64 %0, {%1, %2};" : "=l"(r) : "f"(x), "f"(y));
    return r;
}
__device__ __forceinline__ float2 unpack2(ull v) {
    float2 f;
    asm("mov.b64 {%0, %1}, %2;" : "=f"(f.x), "=f"(f.y) : "l"(v));
    return f;
}
__device__ __forceinline__ float sigmoidf_(float x) {
    return 1.0f / (1.0f + __expf(-x));
}

// ---------------- 1. zero state (graph-replay idempotence) -----------------
__global__ void zero_state() {
    int i = blockIdx.x * blockDim.x + threadIdx.x;
    if (i < HID * BATCH) { g_H0[i] = 0.0f; g_C[i] = 0.0f; }
}

// ---------------- 2. pack weights ------------------------------------------
// Wx: [k][c] with c = h*4+g.   Wh: [cb][k][cc] with c = cb*32+cc = h*4+g.
__global__ void pack_weights(const float* Wxi, const float* Wxf, const float* Wxc, const float* Wxo,
                             const float* Whi, const float* Whf, const float* Whc, const float* Who,
                             const float* bi,  const float* bf,  const float* bc,  const float* bo) {
    const float* Wx[4] = {Wxi, Wxf, Wxc, Wxo};
    const float* Wh[4] = {Whi, Whf, Whc, Who};
    const float* bb[4] = {bi, bf, bc, bo};
    int stride = gridDim.x * blockDim.x;
    int tid0   = blockIdx.x * blockDim.x + threadIdx.x;
    for (int idx = tid0; idx < 4 * HID * HID; idx += stride) {
        int g = idx >> 20, r = idx & ((1 << 20) - 1);
        int k = r >> 10, h = r & 1023;
        int c = (h << 2) + g;
        g_Whp2[(size_t)(c >> 5) * (HID * 32) + k * 32 + (c & 31)] = Wh[g][r];
    }
    for (int idx = tid0; idx < 4 * EMBD * HID; idx += stride) {
        int g = idx >> 19, r = idx & ((1 << 19) - 1);
        int e = r >> 10, h = r & 1023;
        g_Wxp[e * G4 + (h << 2) + g] = Wx[g][r];
    }
    for (int idx = tid0; idx < G4; idx += stride) {
        int g = idx >> 10, h = idx & 1023;
        g_bp[(h << 2) + g] = bb[g][h];
    }
}

// ---------------- 3. phase-1 GEMM: GX = xe @ Wxp + b (unchanged) -----------
#define P1_BM 128
#define P1_BN 64
#define P1_BK 32
__global__ void __launch_bounds__(256) phase1_gemm(const int* xx, const float* emb) {
    __shared__ __align__(16) float As[P1_BK][P1_BM + 4];
    __shared__ __align__(16) float Bs[P1_BK][P1_BN];
    __shared__ const float* rowp[P1_BM];

    int tid = threadIdx.x;
    int r0  = blockIdx.y * P1_BM;
    int c0  = blockIdx.x * P1_BN;

    if (tid < P1_BM) {
        int r = r0 + tid;
        int t = r >> 6, b = r & 63;
        rowp[tid] = emb + (size_t)xx[b * TT + t] * EMBD;
    }
    __syncthreads();

    int tx = tid & 15, ty = tid >> 4;
    ull acc[4][4];
    #pragma unroll
    for (int p = 0; p < 4; p++)
        #pragma unroll
        for (int j = 0; j < 4; j++) acc[p][j] = 0ull;

    int lm = tid >> 1, lh = (tid & 1) * 16;
    int bk = tid >> 3, bc = (tid & 7) * 4;

    for (int k0 = 0; k0 < EMBD; k0 += P1_BK) {
        float4 av[4];
        const float* rp = rowp[lm] + k0 + lh;
        #pragma unroll
        for (int i = 0; i < 4; i++) av[i] = *(const float4*)(rp + 4 * i);
        float4 bv0 = *(const float4*)(g_Wxp + (size_t)(k0 + bk) * G4 + c0 + bc);
        float4 bv1 = *(const float4*)(g_Wxp + (size_t)(k0 + bk) * G4 + c0 + bc + 32);

        __syncthreads();
        #pragma unroll
        for (int i = 0; i < 4; i++) {
            As[lh + 4 * i + 0][lm] = av[i].x;
            As[lh + 4 * i + 1][lm] = av[i].y;
            As[lh + 4 * i + 2][lm] = av[i].z;
            As[lh + 4 * i + 3][lm] = av[i].w;
        }
        *(float4*)&Bs[bk][bc]      = bv0;
        *(float4*)&Bs[bk][bc + 32] = bv1;
        __syncthreads();

        #pragma unroll
        for (int k = 0; k < P1_BK; k++) {
            ulonglong2 a01 = *(const ulonglong2*)&As[k][ty * 8];
            ulonglong2 a23 = *(const ulonglong2*)&As[k][ty * 8 + 4];
            float4 b4 = *(const float4*)&Bs[k][tx * 4];
            ull aav[4] = {a01.x, a01.y, a23.x, a23.y};
            ull bbv[4] = {pack2(b4.x, b4.x), pack2(b4.y, b4.y),
                          pack2(b4.z, b4.z), pack2(b4.w, b4.w)};
            #pragma unroll
            for (int p = 0; p < 4; p++)
                #pragma unroll
                for (int j = 0; j < 4; j++)
                    acc[p][j] = ffma2(aav[p], bbv[j], acc[p][j]);
        }
    }

    float bpv[4];
    #pragma unroll
    for (int j = 0; j < 4; j++) bpv[j] = g_bp[c0 + tx * 4 + j];
    #pragma unroll
    for (int p = 0; p < 4; p++) {
        int m = ty * 8 + 2 * p;
        int r = r0 + m;
        int t = r >> 6, b = r & 63;
        float* base = g_GX + (size_t)t * (G4 * BATCH) + (size_t)(c0 + tx * 4) * BATCH + b;
        #pragma unroll
        for (int j = 0; j < 4; j++) {
            float2 v = unpack2(acc[p][j]);
            v.x += bpv[j]; v.y += bpv[j];
            *(float2*)(base + j * BATCH) = v;
        }
    }
}

// ---------------- 4. one LSTM step -----------------------------------------
// grid 128 (CTA cb = 32 packed cols = 8 h-units), 256 threads = 8 warps.
// Warp w reduces k in [w*128, (w+1)*128); one warp covers the FULL 32x64
// output tile: lane = tx*8+tyb? -> tx = lane>>3 (col-oct), tyb = lane&7
// (batch-oct). Thread tile 8 cols x 8 batch = 32 f32x2 accs (col-pair packed).
// Per lane per k: 64B delivered for 64 MACs (1 B/MAC).
#define KTILE 8
#define NTILE 16   // 128 k per warp / KTILE
__global__ void __launch_bounds__(256, 1) lstm_step(int t) {
    __shared__ __align__(16) float sh_h[8][2][KTILE * 64];   // 32 KB
    __shared__ __align__(16) float sh_w[8][2][KTILE * 32];   // 16 KB

    int tid  = threadIdx.x;
    int wid  = tid >> 5;
    int lane = tid & 31;
    int tx   = lane >> 3;          // col-oct 0..3
    int tyb  = lane & 7;           // batch-oct 0..7
    int c0   = tx * 8;
    int b0   = tyb * 8;
    int cb   = blockIdx.x;
    int h0   = cb * 8;

    const float* hin  = (t & 1) ? g_H1 : g_H0;
    float*       hout = (t & 1) ? g_H0 : g_H1;

    // acc[cp][bj]: f32x2 over cols (c0+2cp, c0+2cp+1) at batch b0+bj
    ull acc[4][8];
    #pragma unroll
    for (int cp = 0; cp < 4; cp++)
        #pragma unroll
        for (int bj = 0; bj < 8; bj++) acc[cp][bj] = 0ull;

    const float* hsrc = hin + (wid * 128) * 64;                       // [128k][64b]
    const float* wsrc = g_Whp2 + (size_t)cb * (HID * 32) + (wid * 128) * 32;

    float4 hr[4], wr[2];
    // preload + store tile 0 (warp-local)
    #pragma unroll
    for (int j = 0; j < 4; j++) hr[j] = *(const float4*)(hsrc + lane * 16 + 4 * j);
    #pragma unroll
    for (int j = 0; j < 2; j++) wr[j] = *(const float4*)(wsrc + lane * 8 + 4 * j);
    #pragma unroll
    for (int j = 0; j < 4; j++) *(float4*)(&sh_h[wid][0][0] + lane * 16 + 4 * j) = hr[j];
    #pragma unroll
    for (int j = 0; j < 2; j++) *(float4*)(&sh_w[wid][0][0] + lane * 8 + 4 * j) = wr[j];
    __syncwarp();

    int cur = 0;
    for (int tile = 0; tile < NTILE; ++tile) {
        if (tile < NTILE - 1) {   // register prefetch of next tile (LDG)
            const float* hp = hsrc + (tile + 1) * (KTILE * 64);
            const float* wp = wsrc + (tile + 1) * (KTILE * 32);
            #pragma unroll
            for (int j = 0; j < 4; j++) hr[j] = *(const float4*)(hp + lane * 16 + 4 * j);
            #pragma unroll
            for (int j = 0; j < 2; j++) wr[j] = *(const float4*)(wp + lane * 8 + 4 * j);
        }
        const float* hb = &sh_h[wid][cur][0];
        const float* wb = &sh_w[wid][cur][0];
        #pragma unroll
        for (int k = 0; k < KTILE; k++) {
            float4 a0 = *(const float4*)(hb + k * 64 + b0);       // batch b0..b0+3
            float4 a1 = *(const float4*)(hb + k * 64 + b0 + 4);   // batch b0+4..b0+7
            ulonglong2 w01 = *(const ulonglong2*)(wb + k * 32 + c0);      // col-pairs 0,1
            ulonglong2 w23 = *(const ulonglong2*)(wb + k * 32 + c0 + 4);  // col-pairs 2,3
            ull s[8];
            s[0] = pack2(a0.x, a0.x); s[1] = pack2(a0.y, a0.y);
            s[2] = pack2(a0.z, a0.z); s[3] = pack2(a0.w, a0.w);
            s[4] = pack2(a1.x, a1.x); s[5] = pack2(a1.y, a1.y);
            s[6] = pack2(a1.z, a1.z); s[7] = pack2(a1.w, a1.w);
            #pragma unroll
            for (int bj = 0; bj < 8; bj++) {
                acc[0][bj] = ffma2(w01.x, s[bj], acc[0][bj]);
                acc[1][bj] = ffma2(w01.y, s[bj], acc[1][bj]);
                acc[2][bj] = ffma2(w23.x, s[bj], acc[2][bj]);
                acc[3][bj] = ffma2(w23.y, s[bj], acc[3][bj]);
            }
        }
        if (tile < NTILE - 1) {
            int nxt = cur ^ 1;
            #pragma unroll
            for (int j = 0; j < 4; j++) *(float4*)(&sh_h[wid][nxt][0] + lane * 16 + 4 * j) = hr[j];
            #pragma unroll
            for (int j = 0; j < 2; j++) *(float4*)(&sh_w[wid][nxt][0] + lane * 8 + 4 * j) = wr[j];
            __syncwarp();
            cur = nxt;
        }
    }

    // ---- combine 8 warp-partials: 8 rounds into aliased smem --------------
    __syncthreads();                                   // staging buffers now free
    ull* Gs = (ull*)&sh_h[0][0][0];                    // 16 col-pairs x 64 b = 8 KB
    #pragma unroll 1
    for (int r = 0; r < 8; r++) {
        if (wid == r) {
            #pragma unroll
            for (int cp = 0; cp < 4; cp++)
                #pragma unroll
                for (int bj = 0; bj < 8; bj++) {
                    int idx = (tx * 4 + cp) * 64 + b0 + bj;
                    Gs[idx] = (r == 0) ? acc[cp][bj] : add2(Gs[idx], acc[cp][bj]);
                }
        }
        __syncthreads();
    }

    // ---- elementwise LSTM cell: g = Gs + gx, then i/f/g/o -----------------
    const float* Gf  = (const float*)Gs;   // Gf[cg*128 + 2b + half], col = 2cg+half
    const float* gxb = g_GX + (size_t)t * (G4 * BATCH) + (size_t)cb * 32 * BATCH;
    for (int ii = tid; ii < 512; ii += 256) {
        int hh = ii >> 6, b = ii & 63;
        float gi = Gf[(2 * hh)     * 128 + 2 * b]     + gxb[(4 * hh + 0) * 64 + b];
        float gf = Gf[(2 * hh)     * 128 + 2 * b + 1] + gxb[(4 * hh + 1) * 64 + b];
        float gc = Gf[(2 * hh + 1) * 128 + 2 * b]     + gxb[(4 * hh + 2) * 64 + b];
        float go = Gf[(2 * hh + 1) * 128 + 2 * b + 1] + gxb[(4 * hh + 3) * 64 + b];
        float iv = sigmoidf_(gi);
        float fv = sigmoidf_(gf);
        float gv = tanhf(gc);
        float ov = sigmoidf_(go);
        int off = (h0 + hh) * 64 + b;
        float c = fv * g_C[off] + iv * gv;
        g_C[off]  = c;
        hout[off] = ov * tanhf(c);
    }
}

// ---------------- 5. output projection: out = h @ Why + by -----------------
__global__ void out_kernel(const float* Why, const float* by, float* out) {
    __shared__ float red[256];
    int b = blockIdx.x >> 1, o = blockIdx.x & 1;
    float s = 0.0f;
    for (int k = threadIdx.x; k < HID; k += 256)
        s += g_H0[k * 64 + b] * Why[k * 2 + o];   // T=512 even -> final h in g_H0
    red[threadIdx.x] = s;
    __syncthreads();
    for (int st = 128; st > 0; st >>= 1) {
        if (threadIdx.x < st) red[threadIdx.x] += red[threadIdx.x + st];
        __syncthreads();
    }
    if (threadIdx.x == 0) out[b * 2 + o] = red[0] + by[o];
}

// ---------------- launch ----------------------------------------------------
extern "C" void kernel_launch(void* const* d_in, const int* in_sizes, int n_in,
                              void* d_out, int out_size) {
    const int*   x   = (const int*)  d_in[0];
    const float* emb = (const float*)d_in[1];
    const float* Wxi = (const float*)d_in[2];
    const float* Whi = (const float*)d_in[3];
    const float* bi  = (const float*)d_in[4];
    const float* Wxf = (const float*)d_in[5];
    const float* Whf = (const float*)d_in[6];
    const float* bf  = (const float*)d_in[7];
    const float* Wxc = (const float*)d_in[8];
    const float* Whc = (const float*)d_in[9];
    const float* bc  = (const float*)d_in[10];
    const float* Wxo = (const float*)d_in[11];
    const float* Who = (const float*)d_in[12];
    const float* bo  = (const float*)d_in[13];
    const float* Why = (const float*)d_in[14];
    const float* by  = (const float*)d_in[15];
    float* out = (float*)d_out;

    zero_state<<<256, 256>>>();
    pack_weights<<<2048, 256>>>(Wxi, Wxf, Wxc, Wxo, Whi, Whf, Whc, Who, bi, bf, bc, bo);

    dim3 g1(G4 / P1_BN, (TT * BATCH) / P1_BM);   // (64, 256)
    phase1_gemm<<<g1, 256>>>(x, emb);

    for (int t = 0; t < TT; ++t)
        lstm_step<<<128, 256>>>(t);

    out_kernel<<<128, 256>>>(Why, by, out);
}

// round 17
// speedup vs baseline: 2.3413x; 2.3413x over previous
#include <cuda_runtime.h>
#include <cuda_bf16.h>

// LSTM forward, GB300 sm_103a.
// R16: recurrence moved from FFMA2 (stuck at 31-55us/step across 4 designs)
// to tensor cores: mma.sync.m16n8k16 bf16 with 3xBF16 hi/lo split
// (hi@hi + hi@lo + lo@hi, f32 accum) => ~fp32-grade precision (~2^-18/product).
// Weights pre-split in pack; h split in the step epilogue. Each warp owns a
// full-K (m16 x n16) tile => no cross-warp reduction. Phase-1 GEMM unchanged.

#define BATCH 64
#define TT    512
#define EMBD  512
#define HID   1024
#define G4    4096

typedef unsigned long long ull;
typedef unsigned int u32;

// ---------------- device scratch (static only — harness rule) --------------
__device__ float g_Wxp[EMBD * G4];                    //  8 MB packed Wx [k][c]
__device__ __nv_bfloat16 g_Whh[128 * 32 * HID];       //  8 MB Wh hi [cb][cc][k]
__device__ __nv_bfloat16 g_Whl[128 * 32 * HID];       //  8 MB Wh lo
__device__ float g_bp[G4];
__device__ float g_GX[(size_t)TT * G4 * BATCH];       // 512 MB gates_x (+bias) [t][c][b]
__device__ __nv_bfloat16 g_Hh[2][BATCH * HID];        // h hi, [b][k], ping/pong
__device__ __nv_bfloat16 g_Hl[2][BATCH * HID];        // h lo
__device__ float g_Hf[HID * BATCH];                   // fp32 h (latest), [k][b]
__device__ float g_C [HID * BATCH];                   // cT [k][b]

// ---------------- helpers ---------------------------------------------------
__device__ __forceinline__ ull ffma2(ull a, ull b, ull c) {
    ull d;
    asm("fma.rn.f32x2 %0, %1, %2, %3;" : "=l"(d) : "l"(a), "l"(b), "l"(c));
    return d;
}
__device__ __forceinline__ ull pack2(float x, float y) {
    ull r;
    asm("mov.b64 %0, {%1, %2};" : "=l"(r) : "f"(x), "f"(y));
    return r;
}
__device__ __forceinline__ float2 unpack2(ull v) {
    float2 f;
    asm("mov.b64 {%0, %1}, %2;" : "=f"(f.x), "=f"(f.y) : "l"(v));
    return f;
}
__device__ __forceinline__ float sigmoidf_(float x) {
    return 1.0f / (1.0f + __expf(-x));
}
// D += A(16x16 bf16, row) @ B(16x8 bf16, col), f32 accum
__device__ __forceinline__ void mma16816(float* d, const u32* a, const u32* b) {
    asm("mma.sync.aligned.m16n8k16.row.col.f32.bf16.bf16.f32 "
        "{%0,%1,%2,%3}, {%4,%5,%6,%7}, {%8,%9}, {%0,%1,%2,%3};"
        : "+f"(d[0]), "+f"(d[1]), "+f"(d[2]), "+f"(d[3])
        : "r"(a[0]), "r"(a[1]), "r"(a[2]), "r"(a[3]), "r"(b[0]), "r"(b[1]));
}

// ---------------- 1. zero state (graph-replay idempotence) -----------------
__global__ void zero_state() {
    int i = blockIdx.x * blockDim.x + threadIdx.x;
    if (i < BATCH * HID) {
        g_Hh[0][i] = __float2bfloat16(0.0f);
        g_Hl[0][i] = __float2bfloat16(0.0f);
        g_C[i] = 0.0f;
    }
}

// ---------------- 2. pack weights ------------------------------------------
// Wx: [k][c], c = h*4+g.  Wh: bf16 hi/lo, [cb][cc][k] with c = cb*32+cc.
__global__ void pack_weights(const float* Wxi, const float* Wxf, const float* Wxc, const float* Wxo,
                             const float* Whi, const float* Whf, const float* Whc, const float* Who,
                             const float* bi,  const float* bf,  const float* bc,  const float* bo) {
    const float* Wx[4] = {Wxi, Wxf, Wxc, Wxo};
    const float* Wh[4] = {Whi, Whf, Whc, Who};
    const float* bb[4] = {bi, bf, bc, bo};
    int stride = gridDim.x * blockDim.x;
    int tid0   = blockIdx.x * blockDim.x + threadIdx.x;
    for (int idx = tid0; idx < 4 * HID * HID; idx += stride) {
        int g = idx >> 20, r = idx & ((1 << 20) - 1);
        int k = r >> 10, h = r & 1023;
        int c = (h << 2) + g;
        float v = Wh[g][r];
        __nv_bfloat16 hi = __float2bfloat16(v);
        __nv_bfloat16 lo = __float2bfloat16(v - __bfloat162float(hi));
        size_t dst = (size_t)(c >> 5) * (32 * HID) + (size_t)(c & 31) * HID + k;
        g_Whh[dst] = hi;
        g_Whl[dst] = lo;
    }
    for (int idx = tid0; idx < 4 * EMBD * HID; idx += stride) {
        int g = idx >> 19, r = idx & ((1 << 19) - 1);
        int e = r >> 10, h = r & 1023;
        g_Wxp[e * G4 + (h << 2) + g] = Wx[g][r];
    }
    for (int idx = tid0; idx < G4; idx += stride) {
        int g = idx >> 10, h = idx & 1023;
        g_bp[(h << 2) + g] = bb[g][h];
    }
}

// ---------------- 3. phase-1 GEMM: GX = xe @ Wxp + b (unchanged) -----------
#define P1_BM 128
#define P1_BN 64
#define P1_BK 32
__global__ void __launch_bounds__(256) phase1_gemm(const int* xx, const float* emb) {
    __shared__ __align__(16) float As[P1_BK][P1_BM + 4];
    __shared__ __align__(16) float Bs[P1_BK][P1_BN];
    __shared__ const float* rowp[P1_BM];

    int tid = threadIdx.x;
    int r0  = blockIdx.y * P1_BM;
    int c0  = blockIdx.x * P1_BN;

    if (tid < P1_BM) {
        int r = r0 + tid;
        int t = r >> 6, b = r & 63;
        rowp[tid] = emb + (size_t)xx[b * TT + t] * EMBD;
    }
    __syncthreads();

    int tx = tid & 15, ty = tid >> 4;
    ull acc[4][4];
    #pragma unroll
    for (int p = 0; p < 4; p++)
        #pragma unroll
        for (int j = 0; j < 4; j++) acc[p][j] = 0ull;

    int lm = tid >> 1, lh = (tid & 1) * 16;
    int bk = tid >> 3, bc = (tid & 7) * 4;

    for (int k0 = 0; k0 < EMBD; k0 += P1_BK) {
        float4 av[4];
        const float* rp = rowp[lm] + k0 + lh;
        #pragma unroll
        for (int i = 0; i < 4; i++) av[i] = *(const float4*)(rp + 4 * i);
        float4 bv0 = *(const float4*)(g_Wxp + (size_t)(k0 + bk) * G4 + c0 + bc);
        float4 bv1 = *(const float4*)(g_Wxp + (size_t)(k0 + bk) * G4 + c0 + bc + 32);

        __syncthreads();
        #pragma unroll
        for (int i = 0; i < 4; i++) {
            As[lh + 4 * i + 0][lm] = av[i].x;
            As[lh + 4 * i + 1][lm] = av[i].y;
            As[lh + 4 * i + 2][lm] = av[i].z;
            As[lh + 4 * i + 3][lm] = av[i].w;
        }
        *(float4*)&Bs[bk][bc]      = bv0;
        *(float4*)&Bs[bk][bc + 32] = bv1;
        __syncthreads();

        #pragma unroll
        for (int k = 0; k < P1_BK; k++) {
            ulonglong2 a01 = *(const ulonglong2*)&As[k][ty * 8];
            ulonglong2 a23 = *(const ulonglong2*)&As[k][ty * 8 + 4];
            float4 b4 = *(const float4*)&Bs[k][tx * 4];
            ull aav[4] = {a01.x, a01.y, a23.x, a23.y};
            ull bbv[4] = {pack2(b4.x, b4.x), pack2(b4.y, b4.y),
                          pack2(b4.z, b4.z), pack2(b4.w, b4.w)};
            #pragma unroll
            for (int p = 0; p < 4; p++)
                #pragma unroll
                for (int j = 0; j < 4; j++)
                    acc[p][j] = ffma2(aav[p], bbv[j], acc[p][j]);
        }
    }

    float bpv[4];
    #pragma unroll
    for (int j = 0; j < 4; j++) bpv[j] = g_bp[c0 + tx * 4 + j];
    #pragma unroll
    for (int p = 0; p < 4; p++) {
        int m = ty * 8 + 2 * p;
        int r = r0 + m;
        int t = r >> 6, b = r & 63;
        float* base = g_GX + (size_t)t * (G4 * BATCH) + (size_t)(c0 + tx * 4) * BATCH + b;
        #pragma unroll
        for (int j = 0; j < 4; j++) {
            float2 v = unpack2(acc[p][j]);
            v.x += bpv[j]; v.y += bpv[j];
            *(float2*)(base + j * BATCH) = v;
        }
    }
}

// ---------------- 4. one LSTM step (tensor-core 3xBF16) --------------------
// grid 128 (CTA cb: 32 packed cols), 256 thr = 8 warps = 4 m-tiles x 2 n-halves.
// Warp: m16 (batch) x n16 (cols) x FULL K=1024. 32 k-stages of 32 (double buf).
// smem per buffer: Ah 64x40, Al 64x40, Bh 32x40, Bl 32x40 bf16 (+8 pad => 
// conflict-free frag LDS). Epilogue: accs -> smem Gs[32][64], + gx, cell math,
// write h as bf16 hi/lo ([b][k]) + fp32 ([k][b]).
__global__ void __launch_bounds__(256, 1) lstm_step(int t) {
    __shared__ __align__(16) unsigned char sm[2][15360];

    int tid  = threadIdx.x;
    int lane = tid & 31, wid = tid >> 5;
    int m0 = (wid & 3) * 16;          // batch tile
    int n0 = (wid >> 2) * 16;         // col half
    int cb = blockIdx.x;
    int fr = lane >> 2;               // frag row / B n
    int fc = (lane & 3) * 2;          // frag col pair

    const __nv_bfloat16* Hh = g_Hh[t & 1];
    const __nv_bfloat16* Hl = g_Hl[t & 1];
    __nv_bfloat16* Hho = g_Hh[(t & 1) ^ 1];
    __nv_bfloat16* Hlo = g_Hl[(t & 1) ^ 1];

    float acc[2][4];
    #pragma unroll
    for (int tn = 0; tn < 2; tn++)
        #pragma unroll
        for (int j = 0; j < 4; j++) acc[tn][j] = 0.0f;

    // staging coords: A rows 64 x 32 bf16 (4 x uint4 segs), B rows 32 x 32
    int arow = tid >> 2, aseg = (tid & 3) * 8;
    int brow = tid >> 3, bseg = (tid & 7) * 4;
    const __nv_bfloat16* whh = g_Whh + (size_t)cb * (32 * HID);
    const __nv_bfloat16* whl = g_Whl + (size_t)cb * (32 * HID);

    // prologue: stage 0
    uint4 rah = *(const uint4*)(Hh + arow * HID + aseg);
    uint4 ral = *(const uint4*)(Hl + arow * HID + aseg);
    uint2 rbh = *(const uint2*)(whh + brow * HID + bseg);
    uint2 rbl = *(const uint2*)(whl + brow * HID + bseg);
    {
        __nv_bfloat16* D = (__nv_bfloat16*)sm[0];
        *(uint4*)(D + arow * 40 + aseg)        = rah;
        *(uint4*)(D + 2560 + arow * 40 + aseg) = ral;
        *(uint2*)(D + 5120 + brow * 40 + bseg) = rbh;
        *(uint2*)(D + 6400 + brow * 40 + bseg) = rbl;
    }
    __syncthreads();

    int cur = 0;
    #pragma unroll 1
    for (int s = 0; s < 32; s++) {
        if (s < 31) {   // prefetch next stage
            int k0 = (s + 1) * 32;
            rah = *(const uint4*)(Hh + arow * HID + k0 + aseg);
            ral = *(const uint4*)(Hl + arow * HID + k0 + aseg);
            rbh = *(const uint2*)(whh + brow * HID + k0 + bseg);
            rbl = *(const uint2*)(whl + brow * HID + k0 + bseg);
        }
        const __nv_bfloat16* AH = (const __nv_bfloat16*)sm[cur];
        const __nv_bfloat16* AL = AH + 2560;
        const __nv_bfloat16* BH = AH + 5120;
        const __nv_bfloat16* BL = AH + 6400;
        #pragma unroll
        for (int kc = 0; kc < 32; kc += 16) {
            u32 ah[4], al[4];
            ah[0] = *(const u32*)(AH + (m0 + fr)     * 40 + kc + fc);
            ah[1] = *(const u32*)(AH + (m0 + fr + 8) * 40 + kc + fc);
            ah[2] = *(const u32*)(AH + (m0 + fr)     * 40 + kc + fc + 8);
            ah[3] = *(const u32*)(AH + (m0 + fr + 8) * 40 + kc + fc + 8);
            al[0] = *(const u32*)(AL + (m0 + fr)     * 40 + kc + fc);
            al[1] = *(const u32*)(AL + (m0 + fr + 8) * 40 + kc + fc);
            al[2] = *(const u32*)(AL + (m0 + fr)     * 40 + kc + fc + 8);
            al[3] = *(const u32*)(AL + (m0 + fr + 8) * 40 + kc + fc + 8);
            #pragma unroll
            for (int tn = 0; tn < 2; tn++) {
                int nr = (n0 + tn * 8 + fr) * 40 + kc + fc;
                u32 bh[2], bl[2];
                bh[0] = *(const u32*)(BH + nr);
                bh[1] = *(const u32*)(BH + nr + 8);
                bl[0] = *(const u32*)(BL + nr);
                bl[1] = *(const u32*)(BL + nr + 8);
                mma16816(acc[tn], ah, bh);
                mma16816(acc[tn], ah, bl);
                mma16816(acc[tn], al, bh);
            }
        }
        if (s < 31) {
            int nxt = cur ^ 1;
            __nv_bfloat16* D = (__nv_bfloat16*)sm[nxt];
            *(uint4*)(D + arow * 40 + aseg)        = rah;
            *(uint4*)(D + 2560 + arow * 40 + aseg) = ral;
            *(uint2*)(D + 5120 + brow * 40 + bseg) = rbh;
            *(uint2*)(D + 6400 + brow * 40 + bseg) = rbl;
            __syncthreads();
            cur = nxt;
        }
    }

    // ---- epilogue: frags -> Gs[c][b], + gx, cell math ----
    __syncthreads();
    float* Gs = (float*)sm;                 // 32 x 64 f32 = 8 KB
    #pragma unroll
    for (int tn = 0; tn < 2; tn++) {
        int cA = n0 + tn * 8 + fc;
        int bA = m0 + fr;
        Gs[(cA)     * 64 + bA]     = acc[tn][0];
        Gs[(cA + 1) * 64 + bA]     = acc[tn][1];
        Gs[(cA)     * 64 + bA + 8] = acc[tn][2];
        Gs[(cA + 1) * 64 + bA + 8] = acc[tn][3];
    }
    __syncthreads();

    const float* gxb = g_GX + (size_t)t * (G4 * BATCH) + (size_t)cb * 32 * BATCH;
    for (int ii = tid; ii < 512; ii += 256) {
        int hh = ii >> 6, b = ii & 63;
        float gi = Gs[(4 * hh + 0) * 64 + b] + gxb[(4 * hh + 0) * 64 + b];
        float gf = Gs[(4 * hh + 1) * 64 + b] + gxb[(4 * hh + 1) * 64 + b];
        float gc = Gs[(4 * hh + 2) * 64 + b] + gxb[(4 * hh + 2) * 64 + b];
        float go = Gs[(4 * hh + 3) * 64 + b] + gxb[(4 * hh + 3) * 64 + b];
        float iv = sigmoidf_(gi);
        float fv = sigmoidf_(gf);
        float gv = tanhf(gc);
        float ov = sigmoidf_(go);
        int kidx = cb * 8 + hh;
        float c = fv * g_C[kidx * 64 + b] + iv * gv;
        g_C[kidx * 64 + b] = c;
        float hval = ov * tanhf(c);
        g_Hf[kidx * 64 + b] = hval;
        __nv_bfloat16 hhi = __float2bfloat16(hval);
        Hho[b * HID + kidx] = hhi;
        Hlo[b * HID + kidx] = __float2bfloat16(hval - __bfloat162float(hhi));
    }
}

// ---------------- 5. output projection: out = h @ Why + by -----------------
__global__ void out_kernel(const float* Why, const float* by, float* out) {
    __shared__ float red[256];
    int b = blockIdx.x >> 1, o = blockIdx.x & 1;
    float s = 0.0f;
    for (int k = threadIdx.x; k < HID; k += 256)
        s += g_Hf[k * 64 + b] * Why[k * 2 + o];
    red[threadIdx.x] = s;
    __syncthreads();
    for (int st = 128; st > 0; st >>= 1) {
        if (threadIdx.x < st) red[threadIdx.x] += red[threadIdx.x + st];
        __syncthreads();
    }
    if (threadIdx.x == 0) out[b * 2 + o] = red[0] + by[o];
}

// ---------------- launch ----------------------------------------------------
extern "C" void kernel_launch(void* const* d_in, const int* in_sizes, int n_in,
                              void* d_out, int out_size) {
    const int*   x   = (const int*)  d_in[0];
    const float* emb = (const float*)d_in[1];
    const float* Wxi = (const float*)d_in[2];
    const float* Whi = (const float*)d_in[3];
    const float* bi  = (const float*)d_in[4];
    const float* Wxf = (const float*)d_in[5];
    const float* Whf = (const float*)d_in[6];
    const float* bf  = (const float*)d_in[7];
    const float* Wxc = (const float*)d_in[8];
    const float* Whc = (const float*)d_in[9];
    const float* bc  = (const float*)d_in[10];
    const float* Wxo = (const float*)d_in[11];
    const float* Who = (const float*)d_in[12];
    const float* bo  = (const float*)d_in[13];
    const float* Why = (const float*)d_in[14];
    const float* by  = (const float*)d_in[15];
    float* out = (float*)d_out;

    zero_state<<<256, 256>>>();
    pack_weights<<<2048, 256>>>(Wxi, Wxf, Wxc, Wxo, Whi, Whf, Whc, Who, bi, bf, bc, bo);

    dim3 g1(G4 / P1_BN, (TT * BATCH) / P1_BM);   // (64, 256)
    phase1_gemm<<<g1, 256>>>(x, emb);

    for (int t = 0; t < TT; ++t)
        lstm_step<<<128, 256>>>(t);

    out_kernel<<<128, 256>>>(Why, by, out);
}